// round 15
// baseline (speedup 1.0000x reference)
#include <cuda_runtime.h>

#define NB       4096        // batch (selection axis)
#define NT       256         // T
#define ND       64          // D
#define NCOL     (NT * ND)   // 16384 columns per tensor
#define KRANK    204         // int(0.05 * 4096), 0-based rank
#define G        16          // columns per block (4 float4 columns = 64 B/row)
#define CAPC     416         // candidate capacity per column (mean 301, sd 16.7)
#define NTHREADS 256
#define NWARP    8
#define NBLOCKS  (2 * NT * (ND / G))   // 2048

__device__ float    g_var[2 * NCOL];
__device__ unsigned g_done = 0;

static __device__ __forceinline__ unsigned key_of(float f) {
    unsigned u = __float_as_uint(f);
    unsigned mask = (unsigned)((int)u >> 31) | 0x80000000u;
    return u ^ mask;  // monotone: key order == float ascending order
}
static __device__ __forceinline__ float float_of(unsigned k) {
    unsigned mask = (k & 0x80000000u) ? 0x80000000u : 0xFFFFFFFFu;
    return __uint_as_float(k ^ mask);
}

// find the 256-bin bucket containing 0-based rank k; k becomes rank-in-bucket.
// cc[i] = count of bin (lane*8 + i). Warp-collective.
static __device__ __forceinline__ unsigned find_bucket(const unsigned cc[8], int& kk, int lane) {
    unsigned lanesum = 0;
    #pragma unroll
    for (int i = 0; i < 8; i++) lanesum += cc[i];
    unsigned s = lanesum;
    #pragma unroll
    for (int off = 1; off < 32; off <<= 1) {
        unsigned n = __shfl_up_sync(0xffffffffu, s, off);
        if (lane >= off) s += n;
    }
    unsigned run = s - lanesum;  // exclusive prefix over lanes
    int bucket = -1, nk = 0;
    #pragma unroll
    for (int i = 0; i < 8; i++) {
        if (bucket < 0 && (unsigned)kk >= run && (unsigned)kk < run + cc[i]) {
            bucket = lane * 8 + i;
            nk = kk - (int)run;
        }
        run += cc[i];
    }
    unsigned bal = __ballot_sync(0xffffffffu, bucket >= 0);
    int srcl = __ffs(bal) - 1;
    int bb = __shfl_sync(0xffffffffu, bucket, srcl);
    kk = __shfl_sync(0xffffffffu, nk, srcl);
    return (unsigned)bb;
}

__global__ void __launch_bounds__(NTHREADS, 5)
select_kernel(const float* __restrict__ xf, const float* __restrict__ xr,
              float* __restrict__ out) {
    extern __shared__ unsigned smem[];
    unsigned*       seg  = smem;                              // [G][CAPC]
    unsigned*       scnt = smem + G * CAPC;                   // [G]
    unsigned short* hist = (unsigned short*)(smem + G * CAPC + G);  // [NWARP][256] u16

    const int tid  = threadIdx.x;
    const int lane = tid & 31;
    const int w    = tid >> 5;

    const int bid    = blockIdx.x;               // 2048 blocks
    const int tensor = bid >> 10;
    const int rem    = bid & 1023;
    const int t      = rem >> 2;
    const int dgrp   = rem & 3;                  // which group of 16 columns

    const float* src = tensor ? xr : xf;
    const int c = tid & 3;                       // this thread's float4-column (0..3)
    const float4* p = reinterpret_cast<const float4*>(src) + (t * 16 + dgrp * 4 + c)
                      + (size_t)(tid >> 2) * (NCOL / 4);
    const float THR = -1.45f;

    if (tid < G) scnt[tid] = 0;
    __syncthreads();

    // hoisted per-jj column pointers (col = c*4+jj)
    unsigned* cntp[4];
    unsigned* segp[4];
    #pragma unroll
    for (int jj = 0; jj < 4; jj++) {
        cntp[jj] = &scnt[c * 4 + jj];
        segp[jj] = &seg[(c * 4 + jj) * CAPC];
    }

    // ---- software-pipelined streaming load + sparse atomic capture ----
    // (R12/R14 structure, frozen: every restructure attempt lost to it.)
    float4 bufA[4], bufB[4];
    #pragma unroll
    for (int u = 0; u < 4; u++)
        bufA[u] = __ldg(p + (size_t)(u * 64) * (NCOL / 4));

    #pragma unroll 1
    for (int it = 0; it < 64; it += 8) {
        #pragma unroll
        for (int u = 0; u < 4; u++)
            bufB[u] = __ldg(p + (size_t)((it + 4 + u) * 64) * (NCOL / 4));
        #pragma unroll
        for (int u = 0; u < 4; u++) {
            float vv[4] = {bufA[u].x, bufA[u].y, bufA[u].z, bufA[u].w};
            #pragma unroll
            for (int jj = 0; jj < 4; jj++) {
                float v = vv[jj];
                if (v < THR) {
                    unsigned slot = atomicAdd(cntp[jj], 1u);
                    if (slot < CAPC) segp[jj][slot] = ~__float_as_uint(v);
                }
            }
        }
        if (it + 8 < 64) {
            #pragma unroll
            for (int u = 0; u < 4; u++)
                bufA[u] = __ldg(p + (size_t)((it + 8 + u) * 64) * (NCOL / 4));
        }
        #pragma unroll
        for (int u = 0; u < 4; u++) {
            float vv[4] = {bufB[u].x, bufB[u].y, bufB[u].z, bufB[u].w};
            #pragma unroll
            for (int jj = 0; jj < 4; jj++) {
                float v = vv[jj];
                if (v < THR) {
                    unsigned slot = atomicAdd(cntp[jj], 1u);
                    if (slot < CAPC) segp[jj][slot] = ~__float_as_uint(v);
                }
            }
        }
    }
    __syncthreads();

    // ---- select: warp w owns columns w and w+8, flat candidate arrays ----
    unsigned short* h   = hist + w * 256;
    unsigned*       h32 = (unsigned*)h;          // for zeroing (128 words)
    const unsigned  lmlt = (1u << lane) - 1u;

    for (int cc2 = 0; cc2 < 2; cc2++) {
        const int col = w + cc2 * NWARP;
        unsigned* colb = seg + col * CAPC;
        const int cnt0 = (int)scnt[col];

        unsigned prefix = 0;
        int k = KRANK;

        if (cnt0 > KRANK && cnt0 <= CAPC) {
            int cntf = cnt0;
            for (int shift = 24; shift >= 0; shift -= 8) {
                #pragma unroll
                for (int i = 0; i < 4; i++) h32[i * 32 + lane] = 0;
                __syncwarp();
                for (int i0 = 0; i0 < cntf; i0 += 32) {
                    int i = i0 + lane;
                    bool a = i < cntf;
                    unsigned key = a ? colb[i] : 0u;
                    unsigned m = __ballot_sync(0xffffffffu, a);
                    if (a) {
                        unsigned bin = (key >> shift) & 255u;
                        unsigned peers = __match_any_sync(m, bin);
                        if (lane == __ffs(peers) - 1)
                            h[bin] = (unsigned short)(h[bin] + __popc(peers));
                    }
                }
                __syncwarp();
                unsigned c8[8];
                #pragma unroll
                for (int i = 0; i < 8; i++) c8[i] = h[lane * 8 + i];
                unsigned bucket = find_bucket(c8, k, lane);
                prefix |= bucket << shift;
                if (shift > 0) {
                    // in-place compaction; writes never pass the read frontier
                    int np = 0;
                    for (int i0 = 0; i0 < cntf; i0 += 32) {
                        int i = i0 + lane;
                        bool a = i < cntf;
                        unsigned key = a ? colb[i] : 0u;
                        bool ok = a && (((key >> shift) & 255u) == bucket);
                        unsigned m = __ballot_sync(0xffffffffu, ok);
                        if (ok) colb[np + __popc(m & lmlt)] = key;
                        np += __popc(m);
                    }
                    cntf = np;
                }
            }
        } else {
            // exact fallback (astronomically rare): 4-pass radix re-reading global
            const int cglob = t * 64 + dgrp * 16 + col;
            for (int shift = 24; shift >= 0; shift -= 8) {
                #pragma unroll
                for (int i = 0; i < 4; i++) h32[i * 32 + lane] = 0;
                __syncwarp();
                for (int i = lane; i < NB; i += 32) {
                    unsigned key = key_of(__ldg(src + (size_t)i * NCOL + cglob));
                    bool act = (shift == 24) ||
                               ((key >> (shift + 8)) == (prefix >> (shift + 8)));
                    unsigned m = __ballot_sync(0xffffffffu, act);
                    if (act) {
                        unsigned bin = (key >> shift) & 255u;
                        unsigned peers = __match_any_sync(m, bin);
                        if (lane == __ffs(peers) - 1)
                            h[bin] = (unsigned short)(h[bin] + __popc(peers));
                    }
                }
                __syncwarp();
                unsigned c8[8];
                #pragma unroll
                for (int i = 0; i < 8; i++) c8[i] = h[lane * 8 + i];
                unsigned bucket = find_bucket(c8, k, lane);
                prefix |= bucket << shift;
            }
        }

        if (lane == 0)
            g_var[tensor * NCOL + t * ND + dgrp * G + col] = float_of(prefix);
    }

    // ---- fused reduction: last block standing does the (deterministic) sum ----
    __shared__ unsigned s_last;
    __syncthreads();                 // all g_var stores of this block issued
    if (tid == 0) {
        __threadfence();             // make them visible before counting in
        s_last = (atomicAdd(&g_done, 1u) == NBLOCKS - 1u) ? 1u : 0u;
    }
    __syncthreads();
    if (s_last) {
        __threadfence();             // see all other blocks' g_var stores
        double a = 0.0, r = 0.0;
        #pragma unroll 8
        for (int i = tid; i < NCOL; i += NTHREADS) {   // fixed per-thread order
            float vf = g_var[i];
            float vr = g_var[NCOL + i];
            float d  = fabsf(vf - vr);
            a += (double)d;
            r += (double)(d / (fabsf(vr) + 1e-8f));
        }
        #pragma unroll
        for (int off = 16; off > 0; off >>= 1) {       // fixed shuffle tree
            a += __shfl_down_sync(0xffffffffu, a, off);
            r += __shfl_down_sync(0xffffffffu, r, off);
        }
        __shared__ double sa[NWARP], sr[NWARP];
        if (lane == 0) { sa[w] = a; sr[w] = r; }
        __syncthreads();
        if (tid == 0) {
            double fa = 0.0, fr = 0.0;
            #pragma unroll
            for (int j = 0; j < NWARP; j++) { fa += sa[j]; fr += sr[j]; }  // fixed order
            out[0] = (float)(fa / (double)NCOL);
            out[1] = (float)(fr / (double)NCOL);
            g_done = 0;              // reset for next graph replay
        }
    }
}

extern "C" void kernel_launch(void* const* d_in, const int* in_sizes, int n_in,
                              void* d_out, int out_size) {
    const float* xf = (const float*)d_in[0];
    const float* xr = (const float*)d_in[1];
    const int smem_bytes = (G * CAPC + G) * 4 + NWARP * 256 * 2;  // 30784
    cudaFuncSetAttribute(select_kernel,
                         cudaFuncAttributeMaxDynamicSharedMemorySize, smem_bytes);
    select_kernel<<<NBLOCKS, NTHREADS, smem_bytes>>>(xf, xr, (float*)d_out);
}

// round 16
// speedup vs baseline: 1.2020x; 1.2020x over previous
#include <cuda_runtime.h>

#define NB       4096        // batch (selection axis)
#define NT       256         // T
#define ND       64          // D
#define NCOL     (NT * ND)   // 16384 columns per tensor
#define KRANK    204         // int(0.05 * 4096), 0-based rank
#define G        16          // columns per block (4 float4 columns = 64 B/row)
#define CAPC     416         // candidate capacity per column (mean 301, sd 16.7)
#define NTHREADS 256
#define NWARP    8
#define NBLOCKS  (2 * NT * (ND / G))   // 2048

__device__ float g_var[2 * NCOL];

static __device__ __forceinline__ unsigned key_of(float f) {
    unsigned u = __float_as_uint(f);
    unsigned mask = (unsigned)((int)u >> 31) | 0x80000000u;
    return u ^ mask;  // monotone: key order == float ascending order
}
static __device__ __forceinline__ float float_of(unsigned k) {
    unsigned mask = (k & 0x80000000u) ? 0x80000000u : 0xFFFFFFFFu;
    return __uint_as_float(k ^ mask);
}

// find the 256-bin bucket containing 0-based rank k; k becomes rank-in-bucket.
// cc[i] = count of bin (lane*8 + i). Warp-collective.
static __device__ __forceinline__ unsigned find_bucket(const unsigned cc[8], int& kk, int lane) {
    unsigned lanesum = 0;
    #pragma unroll
    for (int i = 0; i < 8; i++) lanesum += cc[i];
    unsigned s = lanesum;
    #pragma unroll
    for (int off = 1; off < 32; off <<= 1) {
        unsigned n = __shfl_up_sync(0xffffffffu, s, off);
        if (lane >= off) s += n;
    }
    unsigned run = s - lanesum;  // exclusive prefix over lanes
    int bucket = -1, nk = 0;
    #pragma unroll
    for (int i = 0; i < 8; i++) {
        if (bucket < 0 && (unsigned)kk >= run && (unsigned)kk < run + cc[i]) {
            bucket = lane * 8 + i;
            nk = kk - (int)run;
        }
        run += cc[i];
    }
    unsigned bal = __ballot_sync(0xffffffffu, bucket >= 0);
    int srcl = __ffs(bal) - 1;
    int bb = __shfl_sync(0xffffffffu, bucket, srcl);
    kk = __shfl_sync(0xffffffffu, nk, srcl);
    return (unsigned)bb;
}

__global__ void __launch_bounds__(NTHREADS, 5)
select_kernel(const float* __restrict__ xf, const float* __restrict__ xr) {
    extern __shared__ unsigned smem[];
    unsigned*       seg  = smem;                              // [G][CAPC]
    unsigned*       scnt = smem + G * CAPC;                   // [G]
    unsigned short* hist = (unsigned short*)(smem + G * CAPC + G);  // [NWARP][256] u16

    const int tid  = threadIdx.x;
    const int lane = tid & 31;
    const int w    = tid >> 5;

    const int bid    = blockIdx.x;               // 2048 blocks
    const int tensor = bid >> 10;
    const int rem    = bid & 1023;
    const int t      = rem >> 2;
    const int dgrp   = rem & 3;                  // which group of 16 columns

    const float* src = tensor ? xr : xf;
    const int c = tid & 3;                       // this thread's float4-column (0..3)
    const float4* p = reinterpret_cast<const float4*>(src) + (t * 16 + dgrp * 4 + c)
                      + (size_t)(tid >> 2) * (NCOL / 4);
    const float THR = -1.45f;

    if (tid < G) scnt[tid] = 0;
    __syncthreads();

    // hoisted per-jj column pointers (col = c*4+jj)
    unsigned* cntp[4];
    unsigned* segp[4];
    #pragma unroll
    for (int jj = 0; jj < 4; jj++) {
        cntp[jj] = &scnt[c * 4 + jj];
        segp[jj] = &seg[(c * 4 + jj) * CAPC];
    }

    // ---- software-pipelined streaming load + sparse atomic capture ----
    // (R12/R14 structure, frozen: every restructure attempt lost to it.)
    float4 bufA[4], bufB[4];
    #pragma unroll
    for (int u = 0; u < 4; u++)
        bufA[u] = __ldg(p + (size_t)(u * 64) * (NCOL / 4));

    #pragma unroll 1
    for (int it = 0; it < 64; it += 8) {
        #pragma unroll
        for (int u = 0; u < 4; u++)
            bufB[u] = __ldg(p + (size_t)((it + 4 + u) * 64) * (NCOL / 4));
        #pragma unroll
        for (int u = 0; u < 4; u++) {
            float vv[4] = {bufA[u].x, bufA[u].y, bufA[u].z, bufA[u].w};
            #pragma unroll
            for (int jj = 0; jj < 4; jj++) {
                float v = vv[jj];
                if (v < THR) {
                    unsigned slot = atomicAdd(cntp[jj], 1u);
                    if (slot < CAPC) segp[jj][slot] = ~__float_as_uint(v);
                }
            }
        }
        if (it + 8 < 64) {
            #pragma unroll
            for (int u = 0; u < 4; u++)
                bufA[u] = __ldg(p + (size_t)((it + 8 + u) * 64) * (NCOL / 4));
        }
        #pragma unroll
        for (int u = 0; u < 4; u++) {
            float vv[4] = {bufB[u].x, bufB[u].y, bufB[u].z, bufB[u].w};
            #pragma unroll
            for (int jj = 0; jj < 4; jj++) {
                float v = vv[jj];
                if (v < THR) {
                    unsigned slot = atomicAdd(cntp[jj], 1u);
                    if (slot < CAPC) segp[jj][slot] = ~__float_as_uint(v);
                }
            }
        }
    }
    __syncthreads();

    // ---- select: warp w owns columns w and w+8, flat candidate arrays ----
    unsigned short* h   = hist + w * 256;
    unsigned*       h32 = (unsigned*)h;          // for zeroing (128 words)
    const unsigned  lmlt = (1u << lane) - 1u;

    for (int cc2 = 0; cc2 < 2; cc2++) {
        const int col = w + cc2 * NWARP;
        unsigned* colb = seg + col * CAPC;
        const int cnt0 = (int)scnt[col];

        unsigned prefix = 0;
        int k = KRANK;

        if (cnt0 > KRANK && cnt0 <= CAPC) {
            int cntf = cnt0;
            for (int shift = 24; shift >= 0; shift -= 8) {
                #pragma unroll
                for (int i = 0; i < 4; i++) h32[i * 32 + lane] = 0;
                __syncwarp();
                for (int i0 = 0; i0 < cntf; i0 += 32) {
                    int i = i0 + lane;
                    bool a = i < cntf;
                    unsigned key = a ? colb[i] : 0u;
                    unsigned m = __ballot_sync(0xffffffffu, a);
                    if (a) {
                        unsigned bin = (key >> shift) & 255u;
                        unsigned peers = __match_any_sync(m, bin);
                        if (lane == __ffs(peers) - 1)
                            h[bin] = (unsigned short)(h[bin] + __popc(peers));
                    }
                }
                __syncwarp();
                unsigned c8[8];
                #pragma unroll
                for (int i = 0; i < 8; i++) c8[i] = h[lane * 8 + i];
                unsigned bucket = find_bucket(c8, k, lane);
                prefix |= bucket << shift;
                if (shift > 0) {
                    // in-place compaction; writes never pass the read frontier
                    int np = 0;
                    for (int i0 = 0; i0 < cntf; i0 += 32) {
                        int i = i0 + lane;
                        bool a = i < cntf;
                        unsigned key = a ? colb[i] : 0u;
                        bool ok = a && (((key >> shift) & 255u) == bucket);
                        unsigned m = __ballot_sync(0xffffffffu, ok);
                        if (ok) colb[np + __popc(m & lmlt)] = key;
                        np += __popc(m);
                    }
                    cntf = np;
                }
            }
        } else {
            // exact fallback (astronomically rare): 4-pass radix re-reading global
            const int cglob = t * 64 + dgrp * 16 + col;
            for (int shift = 24; shift >= 0; shift -= 8) {
                #pragma unroll
                for (int i = 0; i < 4; i++) h32[i * 32 + lane] = 0;
                __syncwarp();
                for (int i = lane; i < NB; i += 32) {
                    unsigned key = key_of(__ldg(src + (size_t)i * NCOL + cglob));
                    bool act = (shift == 24) ||
                               ((key >> (shift + 8)) == (prefix >> (shift + 8)));
                    unsigned m = __ballot_sync(0xffffffffu, act);
                    if (act) {
                        unsigned bin = (key >> shift) & 255u;
                        unsigned peers = __match_any_sync(m, bin);
                        if (lane == __ffs(peers) - 1)
                            h[bin] = (unsigned short)(h[bin] + __popc(peers));
                    }
                }
                __syncwarp();
                unsigned c8[8];
                #pragma unroll
                for (int i = 0; i < 8; i++) c8[i] = h[lane * 8 + i];
                unsigned bucket = find_bucket(c8, k, lane);
                prefix |= bucket << shift;
            }
        }

        if (lane == 0)
            g_var[tensor * NCOL + t * ND + dgrp * G + col] = float_of(prefix);
    }

    // signal PDL: this block's work is done (NOT a memory fence — the
    // dependent grid's cudaGridDependencySynchronize provides visibility)
    __syncthreads();
    if (tid == 0) cudaTriggerProgrammaticLaunchCompletion();
}

// 16 blocks x 1024 threads: launched with PDL so scheduling overlaps the
// select kernel's tail; grid-sync guarantees g_var visibility before reads.
__global__ void reduce_kernel(float* __restrict__ out) {
    cudaGridDependencySynchronize();

    const int tid  = threadIdx.x;
    const int lane = tid & 31;
    const int wid  = tid >> 5;
    const int i    = blockIdx.x * 1024 + tid;

    float vf = g_var[i];
    float vr = g_var[NCOL + i];
    float d  = fabsf(vf - vr);
    double a = (double)d;
    double r = (double)(d / (fabsf(vr) + 1e-8f));

    #pragma unroll
    for (int off = 16; off > 0; off >>= 1) {
        a += __shfl_down_sync(0xffffffffu, a, off);
        r += __shfl_down_sync(0xffffffffu, r, off);
    }
    __shared__ double sa[32], sr[32];
    if (lane == 0) { sa[wid] = a; sr[wid] = r; }
    __syncthreads();
    if (tid == 0) {
        double fa = 0.0, fr = 0.0;
        #pragma unroll
        for (int j = 1; j < 32; j++) { sa[0] += sa[j]; sr[0] += sr[j]; }
        fa = sa[0]; fr = sr[0];
        // deterministic cross-block accumulation via fixed-slot globals
        __shared__ double dummy;  (void)dummy;
        static __device__ double g_pa[16];
        static __device__ double g_pr[16];
        g_pa[blockIdx.x] = fa;
        g_pr[blockIdx.x] = fr;
        __threadfence();
        static __device__ unsigned g_done2;
        unsigned prev = atomicAdd(&g_done2, 1u);
        if (prev == 15u) {
            __threadfence();
            double ta = 0.0, tr = 0.0;
            #pragma unroll
            for (int j = 0; j < 16; j++) { ta += g_pa[j]; tr += g_pr[j]; }
            out[0] = (float)(ta / (double)NCOL);
            out[1] = (float)(tr / (double)NCOL);
            g_done2 = 0;   // reset for next graph replay
        }
    }
}

extern "C" void kernel_launch(void* const* d_in, const int* in_sizes, int n_in,
                              void* d_out, int out_size) {
    const float* xf = (const float*)d_in[0];
    const float* xr = (const float*)d_in[1];
    const int smem_bytes = (G * CAPC + G) * 4 + NWARP * 256 * 2;  // 30784
    cudaFuncSetAttribute(select_kernel,
                         cudaFuncAttributeMaxDynamicSharedMemorySize, smem_bytes);
    select_kernel<<<NBLOCKS, NTHREADS, smem_bytes>>>(xf, xr);

    // dependent launch with PDL: overlaps reduce's launch latency with the
    // select kernel's final wave
    cudaLaunchConfig_t cfg = {};
    cfg.gridDim = dim3(16, 1, 1);
    cfg.blockDim = dim3(1024, 1, 1);
    cfg.dynamicSmemBytes = 0;
    cfg.stream = 0;
    cudaLaunchAttribute attrs[1];
    attrs[0].id = cudaLaunchAttributeProgrammaticStreamSerialization;
    attrs[0].val.programmaticStreamSerializationAllowed = 1;
    cfg.attrs = attrs;
    cfg.numAttrs = 1;
    float* outp = (float*)d_out;
    cudaLaunchKernelEx(&cfg, reduce_kernel, outp);
}